// round 1
// baseline (speedup 1.0000x reference)
#include <cuda_runtime.h>

#define NROWS 2048
#define DIN 256
#define H 64
#define HP 32   // h pairs

// Scratch for hidden activations, stored pair-major: [hp][n] as float2
__device__ float2 g_agh[HP * NROWS];
__device__ float2 g_abh[HP * NROWS];

typedef unsigned long long u64;

__device__ __forceinline__ u64 f2add(u64 a, u64 b) {
    u64 d; asm("add.rn.f32x2 %0, %1, %2;" : "=l"(d) : "l"(a), "l"(b)); return d;
}
__device__ __forceinline__ u64 f2fma(u64 a, u64 b, u64 c) {
    u64 d; asm("fma.rn.f32x2 %0, %1, %2, %3;" : "=l"(d) : "l"(a), "l"(b), "l"(c)); return d;
}
__device__ __forceinline__ u64 f2relu(u64 s) {
    float lo, hi;
    asm("mov.b64 {%0, %1}, %2;" : "=f"(lo), "=f"(hi) : "l"(s));
    lo = fmaxf(lo, 0.0f);
    hi = fmaxf(hi, 0.0f);
    u64 d; asm("mov.b64 %0, {%1, %2};" : "=l"(d) : "f"(lo), "f"(hi)); return d;
}

// ---------------------------------------------------------------------------
// Kernel 1: hidden = emb @ W1_slice (+ b1 for ag). Writes pair-major [hp][n].
// Block: 256 threads = 32 hp x 8 n-groups; each thread owns 4 n-rows (n=ng+8r),
// 2 accumulators (h=2hp, 2hp+1). K tiled by 64 through smem.
// ---------------------------------------------------------------------------
__global__ void __launch_bounds__(256) hidden_kernel(
    const float* __restrict__ emb, const float* __restrict__ W1,
    const float* __restrict__ b1, int which)
{
    __shared__ float  embs[32][64];     // [n_local][k_local]
    __shared__ float2 w1s[64][32];      // [k_local][hp]

    const int tid = threadIdx.x;
    const int hp  = tid & 31;
    const int ng  = tid >> 5;           // 0..7
    const int n0  = blockIdx.x * 32;
    const int koff = which ? DIN : 0;

    float acc0[4], acc1[4];
    if (which == 0) {
        float2 bv = ((const float2*)b1)[hp];
        #pragma unroll
        for (int r = 0; r < 4; r++) { acc0[r] = bv.x; acc1[r] = bv.y; }
    } else {
        #pragma unroll
        for (int r = 0; r < 4; r++) { acc0[r] = 0.0f; acc1[r] = 0.0f; }
    }

    for (int kb = 0; kb < DIN / 64; kb++) {
        #pragma unroll
        for (int t = 0; t < 8; t++) {
            int idx = tid + t * 256;
            int r = idx >> 6, c = idx & 63;
            embs[r][c] = emb[(n0 + r) * DIN + kb * 64 + c];
        }
        #pragma unroll
        for (int t = 0; t < 8; t++) {
            int idx = tid + t * 256;
            int kk = idx >> 5, h2 = idx & 31;
            w1s[kk][h2] = ((const float2*)(W1 + (size_t)(koff + kb * 64 + kk) * H))[h2];
        }
        __syncthreads();

        #pragma unroll 8
        for (int kk = 0; kk < 64; kk++) {
            float2 w = w1s[kk][hp];
            #pragma unroll
            for (int r = 0; r < 4; r++) {
                float e = embs[ng + 8 * r][kk];
                acc0[r] += e * w.x;
                acc1[r] += e * w.y;
            }
        }
        __syncthreads();
    }

    float2* outh = which ? g_abh : g_agh;
    #pragma unroll
    for (int r = 0; r < 4; r++)
        outh[hp * NROWS + n0 + ng + 8 * r] = make_float2(acc0[r], acc1[r]);
}

// ---------------------------------------------------------------------------
// Kernel 2: out[n,m] = sigmoid( sum_h relu(ag_h[n,h]+ab_h[m,h]) * W2[h] + b2 )
// Block tile 64(n) x 64(m), 256 threads, 4x4 outputs/thread, h processed in
// f32x2 pairs. Smem tiles pair-major [hp][row] for conflict-free LDS.64.
// ---------------------------------------------------------------------------
__global__ void __launch_bounds__(256) outer_kernel(
    const float* __restrict__ W2, const float* __restrict__ b2,
    float* __restrict__ out)
{
    __shared__ float2 ags[HP * 64];    // [hp][n_local]
    __shared__ float2 abss[HP * 64];   // [hp][m_local]
    __shared__ float2 w2s[HP];

    const int tid = threadIdx.x;
    const int n0 = blockIdx.y * 64;
    const int m0 = blockIdx.x * 64;

    #pragma unroll
    for (int t = 0; t < 8; t++) {
        int idx = tid + t * 256;
        int hp = idx >> 6, c = idx & 63;
        ags[idx]  = g_agh[hp * NROWS + n0 + c];
        abss[idx] = g_abh[hp * NROWS + m0 + c];
    }
    if (tid < HP) w2s[tid] = ((const float2*)W2)[tid];
    __syncthreads();

    const int tx = tid & 15;   // m: m_local = tx + 16*j  (conflict-free b loads)
    const int ty = tid >> 4;   // n: n_local = ty*4 + i   (broadcast a loads)

    const u64* agsu = (const u64*)ags;
    const u64* absu = (const u64*)abss;
    const u64* w2u  = (const u64*)w2s;

    u64 acc[4][4];
    #pragma unroll
    for (int i = 0; i < 4; i++)
        #pragma unroll
        for (int j = 0; j < 4; j++) acc[i][j] = 0ull;

    #pragma unroll 4
    for (int hp = 0; hp < HP; hp++) {
        u64 w = w2u[hp];
        u64 a[4], b[4];
        #pragma unroll
        for (int i = 0; i < 4; i++) a[i] = agsu[hp * 64 + ty * 4 + i];
        #pragma unroll
        for (int j = 0; j < 4; j++) b[j] = absu[hp * 64 + tx + 16 * j];
        #pragma unroll
        for (int i = 0; i < 4; i++)
            #pragma unroll
            for (int j = 0; j < 4; j++)
                acc[i][j] = f2fma(f2relu(f2add(a[i], b[j])), w, acc[i][j]);
    }

    const float b2v = *b2;
    #pragma unroll
    for (int i = 0; i < 4; i++) {
        int n = n0 + ty * 4 + i;
        #pragma unroll
        for (int j = 0; j < 4; j++) {
            float lo, hi;
            asm("mov.b64 {%0, %1}, %2;" : "=f"(lo), "=f"(hi) : "l"(acc[i][j]));
            float logit = lo + hi + b2v;
            out[(size_t)n * 2048 + m0 + tx + 16 * j] = 1.0f / (1.0f + __expf(-logit));
        }
    }
}

extern "C" void kernel_launch(void* const* d_in, const int* in_sizes, int n_in,
                              void* d_out, int out_size)
{
    const float* ag = (const float*)d_in[0];
    const float* ab = (const float*)d_in[1];
    const float* W1 = (const float*)d_in[2];
    const float* b1 = (const float*)d_in[3];
    const float* W2 = (const float*)d_in[4];
    const float* b2 = (const float*)d_in[5];
    float* out = (float*)d_out;

    hidden_kernel<<<NROWS / 32, 256>>>(ag, W1, b1, 0);
    hidden_kernel<<<NROWS / 32, 256>>>(ab, W1, b1, 1);

    dim3 grid(2048 / 64, 2048 / 64);
    outer_kernel<<<grid, 256>>>(W2, b2, out);
}

// round 2
// speedup vs baseline: 1.2029x; 1.2029x over previous
#include <cuda_runtime.h>

#define NROWS 2048
#define DIN 256
#define H 64
#define HP 32   // h pairs

// Scratch for hidden activations, stored pair-major: [hp][n] as float2
__device__ float2 g_agh[HP * NROWS];
__device__ float2 g_abh[HP * NROWS];

typedef unsigned long long u64;

__device__ __forceinline__ u64 f2add(u64 a, u64 b) {
    u64 d; asm("add.rn.f32x2 %0, %1, %2;" : "=l"(d) : "l"(a), "l"(b)); return d;
}
__device__ __forceinline__ u64 f2fma(u64 a, u64 b, u64 c) {
    u64 d; asm("fma.rn.f32x2 %0, %1, %2, %3;" : "=l"(d) : "l"(a), "l"(b), "l"(c)); return d;
}
__device__ __forceinline__ u64 f2relu(u64 s) {
    float lo, hi;
    asm("mov.b64 {%0, %1}, %2;" : "=f"(lo), "=f"(hi) : "l"(s));
    lo = fmaxf(lo, 0.0f);
    hi = fmaxf(hi, 0.0f);
    u64 d; asm("mov.b64 %0, {%1, %2};" : "=l"(d) : "f"(lo), "f"(hi)); return d;
}

// ---------------------------------------------------------------------------
// Kernel 1 (fused): hidden activations for BOTH embeddings.
// Grid = 256 blocks: blocks [0,128) -> ag (uses W1[:256], +b1),
//                    blocks [128,256) -> ab (uses W1[256:], no bias).
// Each block: 16 n-rows, all 64 h. 256 threads = 32 hp x 8 ng; each thread
// owns rows {ng, ng+8} and h-pair hp -> 4 scalar accumulators.
// K tiled by 128 through smem (2 iterations). Warp = fixed ng, hp=lane:
//   embs reads broadcast, w1s reads stride-1 float2 (conflict-free).
// ---------------------------------------------------------------------------
__global__ void __launch_bounds__(256) hidden_kernel(
    const float* __restrict__ ag, const float* __restrict__ ab,
    const float* __restrict__ W1, const float* __restrict__ b1)
{
    __shared__ float  embs[16][128];    // [n_local][k_local]   8 KB
    __shared__ float2 w1s[128][32];     // [k_local][hp]       32 KB

    const int tid = threadIdx.x;
    const int hp  = tid & 31;
    const int ng  = tid >> 5;           // 0..7
    const int which = blockIdx.x >> 7;  // 0 = ag, 1 = ab
    const int n0  = (blockIdx.x & 127) * 16;
    const int koff = which ? DIN : 0;
    const float* __restrict__ emb = which ? ab : ag;

    float acc00, acc01, acc10, acc11;
    if (which == 0) {
        float2 bv = ((const float2*)b1)[hp];
        acc00 = bv.x; acc01 = bv.y; acc10 = bv.x; acc11 = bv.y;
    } else {
        acc00 = acc01 = acc10 = acc11 = 0.0f;
    }

    #pragma unroll
    for (int kb = 0; kb < 2; kb++) {
        // emb tile: 16 x 128 floats = 512 float4 -> 2 per thread
        #pragma unroll
        for (int t = 0; t < 2; t++) {
            int idx = tid + t * 256;             // 0..511
            int r = idx >> 5, c4 = idx & 31;     // row 0..15, float4 col 0..31
            ((float4*)&embs[r][c4 * 4])[0] =
                ((const float4*)(emb + (size_t)(n0 + r) * DIN + kb * 128))[c4];
        }
        // W1 tile: 128 x 64 floats = 2048 float4 -> 8 per thread
        #pragma unroll
        for (int t = 0; t < 8; t++) {
            int idx = tid + t * 256;             // 0..2047
            int kk = idx >> 4, q = idx & 15;     // k 0..127, float4 within row
            ((float4*)&w1s[kk][0])[q] =
                ((const float4*)(W1 + (size_t)(koff + kb * 128 + kk) * H))[q];
        }
        __syncthreads();

        #pragma unroll 16
        for (int kk = 0; kk < 128; kk++) {
            float2 w = w1s[kk][hp];
            float e0 = embs[ng][kk];
            float e1 = embs[ng + 8][kk];
            acc00 += e0 * w.x;
            acc01 += e0 * w.y;
            acc10 += e1 * w.x;
            acc11 += e1 * w.y;
        }
        __syncthreads();
    }

    float2* outh = which ? g_abh : g_agh;
    outh[hp * NROWS + n0 + ng]     = make_float2(acc00, acc01);
    outh[hp * NROWS + n0 + ng + 8] = make_float2(acc10, acc11);
}

// ---------------------------------------------------------------------------
// Kernel 2: out[n,m] = sigmoid( sum_h relu(ag_h[n,h]+ab_h[m,h]) * W2[h] + b2 )
// Block tile 64(n) x 64(m), 256 threads, 4x4 outputs/thread, h processed in
// f32x2 pairs. Smem tiles pair-major [hp][row] for conflict-free LDS.64.
// ---------------------------------------------------------------------------
__global__ void __launch_bounds__(256) outer_kernel(
    const float* __restrict__ W2, const float* __restrict__ b2,
    float* __restrict__ out)
{
    __shared__ float2 ags[HP * 64];    // [hp][n_local]
    __shared__ float2 abss[HP * 64];   // [hp][m_local]
    __shared__ float2 w2s[HP];

    const int tid = threadIdx.x;
    const int n0 = blockIdx.y * 64;
    const int m0 = blockIdx.x * 64;

    #pragma unroll
    for (int t = 0; t < 8; t++) {
        int idx = tid + t * 256;
        int hp = idx >> 6, c = idx & 63;
        ags[idx]  = g_agh[hp * NROWS + n0 + c];
        abss[idx] = g_abh[hp * NROWS + m0 + c];
    }
    if (tid < HP) w2s[tid] = ((const float2*)W2)[tid];
    __syncthreads();

    const int tx = tid & 15;   // m: m_local = tx + 16*j  (conflict-free b loads)
    const int ty = tid >> 4;   // n: n_local = ty*4 + i   (broadcast a loads)

    const u64* agsu = (const u64*)ags;
    const u64* absu = (const u64*)abss;
    const u64* w2u  = (const u64*)w2s;

    u64 acc[4][4];
    #pragma unroll
    for (int i = 0; i < 4; i++)
        #pragma unroll
        for (int j = 0; j < 4; j++) acc[i][j] = 0ull;

    #pragma unroll 4
    for (int hp = 0; hp < HP; hp++) {
        u64 w = w2u[hp];
        u64 a[4], b[4];
        #pragma unroll
        for (int i = 0; i < 4; i++) a[i] = agsu[hp * 64 + ty * 4 + i];
        #pragma unroll
        for (int j = 0; j < 4; j++) b[j] = absu[hp * 64 + tx + 16 * j];
        #pragma unroll
        for (int i = 0; i < 4; i++)
            #pragma unroll
            for (int j = 0; j < 4; j++)
                acc[i][j] = f2fma(f2relu(f2add(a[i], b[j])), w, acc[i][j]);
    }

    const float b2v = *b2;
    #pragma unroll
    for (int i = 0; i < 4; i++) {
        int n = n0 + ty * 4 + i;
        #pragma unroll
        for (int j = 0; j < 4; j++) {
            float lo, hi;
            asm("mov.b64 {%0, %1}, %2;" : "=f"(lo), "=f"(hi) : "l"(acc[i][j]));
            float logit = lo + hi + b2v;
            out[(size_t)n * 2048 + m0 + tx + 16 * j] = 1.0f / (1.0f + __expf(-logit));
        }
    }
}

extern "C" void kernel_launch(void* const* d_in, const int* in_sizes, int n_in,
                              void* d_out, int out_size)
{
    const float* ag = (const float*)d_in[0];
    const float* ab = (const float*)d_in[1];
    const float* W1 = (const float*)d_in[2];
    const float* b1 = (const float*)d_in[3];
    const float* W2 = (const float*)d_in[4];
    const float* b2 = (const float*)d_in[5];
    float* out = (float*)d_out;

    hidden_kernel<<<256, 256>>>(ag, ab, W1, b1);

    dim3 grid(2048 / 64, 2048 / 64);
    outer_kernel<<<grid, 256>>>(W2, b2, out);
}